// round 1
// baseline (speedup 1.0000x reference)
#include <cuda_runtime.h>

typedef unsigned long long ull;

#define NEXPERTS 64
#define S_MAX    8192

// static scratch (no allocations allowed)
__device__ float g_part[2u * S_MAX * NEXPERTS];          // split-K partial logits, 4MB
__device__ int   g_idx[S_MAX];
__device__ float g_gate[S_MAX];
__device__ int   g_loc[S_MAX];
__device__ float g_me_partial[(S_MAX / 8) * NEXPERTS];   // per-block softmax sums
__device__ float g_laux;

__device__ __forceinline__ ull pack2(float lo, float hi) {
    ull r; asm("mov.b64 %0, {%1, %2};" : "=l"(r) : "f"(lo), "f"(hi)); return r;
}
__device__ __forceinline__ void ffma2(ull& d, ull a, ull b) {
    asm("fma.rn.f32x2 %0, %1, %2, %0;" : "+l"(d) : "l"(a), "l"(b));
}
__device__ __forceinline__ float2 unpack2(ull v) {
    float2 r; asm("mov.b64 {%0, %1}, %2;" : "=f"(r.x), "=f"(r.y) : "l"(v)); return r;
}

// ---------------------------------------------------------------------------
// Kernel 1: logits = x @ wg^T, split-K=2.
// Tile: 64 tokens x 64 experts, 128 threads, micro 8 tokens x 4 experts.
// Accumulators are f32x2 packed over token pairs (FFMA2 = 2 FMAs/instr).
// ---------------------------------------------------------------------------
__global__ __launch_bounds__(128) void gemm_logits(const float* __restrict__ x,
                                                   const float* __restrict__ wg,
                                                   int D, int S) {
    __shared__ float As[32][68];   // [k][token], padded vs bank conflicts
    __shared__ float Bs[32][68];   // [k][expert]
    const int tid = threadIdx.x;
    const int ty  = tid >> 4;      // 0..7  -> tokens ty*8 .. ty*8+7
    const int tx  = tid & 15;      // 0..15 -> experts tx*4 .. tx*4+3
    const int s0  = blockIdx.x * 64;
    const int half  = D >> 1;
    const int kbase = blockIdx.y * half;

    ull acc[4][4];
#pragma unroll
    for (int i = 0; i < 4; ++i)
#pragma unroll
        for (int j = 0; j < 4; ++j) acc[i][j] = 0ull;

    for (int kt = 0; kt < half; kt += 32) {
#pragma unroll
        for (int r = 0; r < 4; ++r) {
            int i   = tid + r * 128;       // 0..511 float4 groups
            int row = i >> 3;              // 0..63
            int k4  = (i & 7) << 2;        // 0,4,...,28
            float4 av = *(const float4*)(x  + (size_t)(s0 + row) * D + kbase + kt + k4);
            As[k4 + 0][row] = av.x; As[k4 + 1][row] = av.y;
            As[k4 + 2][row] = av.z; As[k4 + 3][row] = av.w;
            float4 bv = *(const float4*)(wg + (size_t)row * D + kbase + kt + k4);
            Bs[k4 + 0][row] = bv.x; Bs[k4 + 1][row] = bv.y;
            Bs[k4 + 2][row] = bv.z; Bs[k4 + 3][row] = bv.w;
        }
        __syncthreads();
#pragma unroll
        for (int k = 0; k < 32; ++k) {
            // token pairs, loaded packed (no movs)
            ulonglong2 A0 = *(const ulonglong2*)&As[k][ty * 8];
            ulonglong2 A1 = *(const ulonglong2*)&As[k][ty * 8 + 4];
            ull a0 = A0.x, a1 = A0.y, a2 = A1.x, a3 = A1.y;
            // expert scalars, duplicated into both f32x2 lanes
            float4 bv = *(const float4*)&Bs[k][tx * 4];
            ull b0 = pack2(bv.x, bv.x), b1 = pack2(bv.y, bv.y);
            ull b2 = pack2(bv.z, bv.z), b3 = pack2(bv.w, bv.w);
            ffma2(acc[0][0], a0, b0); ffma2(acc[0][1], a0, b1);
            ffma2(acc[0][2], a0, b2); ffma2(acc[0][3], a0, b3);
            ffma2(acc[1][0], a1, b0); ffma2(acc[1][1], a1, b1);
            ffma2(acc[1][2], a1, b2); ffma2(acc[1][3], a1, b3);
            ffma2(acc[2][0], a2, b0); ffma2(acc[2][1], a2, b1);
            ffma2(acc[2][2], a2, b2); ffma2(acc[2][3], a2, b3);
            ffma2(acc[3][0], a3, b0); ffma2(acc[3][1], a3, b1);
            ffma2(acc[3][2], a3, b2); ffma2(acc[3][3], a3, b3);
        }
        __syncthreads();
    }

    float* outp = g_part + (size_t)blockIdx.y * S * NEXPERTS;
#pragma unroll
    for (int i = 0; i < 4; ++i) {
        float2 c0 = unpack2(acc[i][0]);
        float2 c1 = unpack2(acc[i][1]);
        float2 c2 = unpack2(acc[i][2]);
        float2 c3 = unpack2(acc[i][3]);
        int t0 = s0 + ty * 8 + 2 * i;
        float4 lo = make_float4(c0.x, c1.x, c2.x, c3.x);
        float4 hi = make_float4(c0.y, c1.y, c2.y, c3.y);
        *(float4*)(outp + (size_t)t0 * NEXPERTS + tx * 4)       = lo;
        *(float4*)(outp + (size_t)(t0 + 1) * NEXPERTS + tx * 4) = hi;
    }
}

// ---------------------------------------------------------------------------
// Kernel 2: per-token softmax over 64 experts, top-1 (first max, like argmax),
// gate = softmax value at argmax = 1/sum(exp(l - max)). One warp per token.
// Also emits deterministic per-block partial sums of gates for l_aux's "me".
// ---------------------------------------------------------------------------
__global__ __launch_bounds__(256) void softmax_top1(int S) {
    __shared__ float gsh[8][64];
    const int warp = threadIdx.x >> 5;
    const int lane = threadIdx.x & 31;
    const int t = blockIdx.x * 8 + warp;

    const float* p0 = g_part + (size_t)t * NEXPERTS;
    const float* p1 = g_part + (size_t)S * NEXPERTS + (size_t)t * NEXPERTS;
    float v0 = p0[lane]      + p1[lane];
    float v1 = p0[lane + 32] + p1[lane + 32];

    float m = fmaxf(v0, v1);
#pragma unroll
    for (int o = 16; o; o >>= 1) m = fmaxf(m, __shfl_xor_sync(0xffffffffu, m, o));
    float e0 = expf(v0 - m), e1 = expf(v1 - m);
    float s = e0 + e1;
#pragma unroll
    for (int o = 16; o; o >>= 1) s += __shfl_xor_sync(0xffffffffu, s, o);

    int ix = 1 << 30;
    if (v1 == m) ix = lane + 32;
    if (v0 == m) ix = lane;          // lower index wins (jnp.argmax semantics)
#pragma unroll
    for (int o = 16; o; o >>= 1) ix = min(ix, __shfl_xor_sync(0xffffffffu, ix, o));

    float inv = 1.0f / s;
    gsh[warp][lane]      = e0 * inv;
    gsh[warp][lane + 32] = e1 * inv;
    if (lane == 0) { g_idx[t] = ix; g_gate[t] = inv; }
    __syncthreads();
    if (threadIdx.x < 64) {
        float acc = 0.f;
#pragma unroll
        for (int w = 0; w < 8; ++w) acc += gsh[w][threadIdx.x];
        g_me_partial[(size_t)blockIdx.x * 64 + threadIdx.x] = acc;
    }
}

// ---------------------------------------------------------------------------
// Kernel 3 (single block, 1024 threads): per-expert ordered rank of each token
// (cumsum of one-hot), total counts (-> ce), me reduction, l_aux.
// Thread (e, g): expert e = tid&63, chunk g = tid>>6 of S/16 tokens.
// Everything reduced in fixed order -> deterministic.
// ---------------------------------------------------------------------------
__global__ __launch_bounds__(1024) void scan_laux(int S, int nb) {
    const int e = threadIdx.x & 63;
    const int g = threadIdx.x >> 6;     // 0..15
    const int chunk = S >> 4;
    const int s0 = g * chunk;

    int cnt = 0;
    for (int s = s0; s < s0 + chunk; ++s) cnt += (g_idx[s] == e);

    __shared__ int   cnt_s[16][64];
    __shared__ float me_s[16][64];
    cnt_s[g][e] = cnt;
    __syncthreads();

    int base = 0, total = 0;
#pragma unroll
    for (int gg = 0; gg < 16; ++gg) {
        int c = cnt_s[gg][e];
        if (gg < g) base += c;
        total += c;
    }
    int run = base;
    for (int s = s0; s < s0 + chunk; ++s)
        if (g_idx[s] == e) g_loc[s] = run++;

    float mp = 0.f;
    for (int b = g; b < nb; b += 16) mp += g_me_partial[(size_t)b * 64 + e];
    me_s[g][e] = mp;
    __syncthreads();
    if (g == 0) {
        float me = 0.f;
#pragma unroll
        for (int gg = 0; gg < 16; ++gg) me += me_s[gg][e];
        me /= (float)S;
        float ce = (float)total / (float)S;   // counts BEFORE capacity drop
        me_s[0][e] = me * ce;
    }
    __syncthreads();
    if (threadIdx.x == 0) {
        float sum = 0.f;
        for (int ee = 0; ee < 64; ++ee) sum += me_s[0][ee];
        g_laux = sum * (float)NEXPERTS;       // mean(me*ce)*E^2 = sum*E
    }
}

// ---------------------------------------------------------------------------
// Kernel 4: scatter the sparse nonzeros into the (memset-zeroed) output.
// ---------------------------------------------------------------------------
__global__ void scatter_out(float* __restrict__ out, int S, int C,
                            long long comb_off, long long disp_off, int write_aux) {
    int s = blockIdx.x * blockDim.x + threadIdx.x;
    if (s == 0 && write_aux) out[0] = g_laux;
    if (s < S) {
        int loc = g_loc[s];
        if (loc < C) {   // token kept (capacity)
            size_t pos = ((size_t)s * NEXPERTS + g_idx[s]) * (size_t)C + loc;
            out[(size_t)comb_off + pos] = g_gate[s];
            if (disp_off >= 0)
                out[(size_t)disp_off + pos] = 1.0f;   // dispatch_mask as 1.0
        }
    }
}

extern "C" void kernel_launch(void* const* d_in, const int* in_sizes, int n_in,
                              void* d_out, int out_size) {
    const float* x  = (const float*)d_in[0];
    const float* wg = (const float*)d_in[1];
    const int D = in_sizes[1] / NEXPERTS;
    const int S = in_sizes[0] / D;
    const int C = (S + NEXPERTS - 1) / NEXPERTS;   // capacity_factor = 1.0
    const size_t SEC = (size_t)S * NEXPERTS * C;
    const size_t osz = (size_t)out_size;

    // output layout: [l_aux(1)][combine(SEC)][dispatch(SEC)] when sizes match
    long long comb = 0, disp = -1; int aux = 0;
    if (osz >= 2 * SEC + 1)      { aux = 1; comb = 1; disp = 1 + (long long)SEC; }
    else if (osz >= 2 * SEC)     { comb = 0; disp = (long long)SEC; }
    // else: combine only at offset 0

    cudaMemsetAsync(d_out, 0, osz * sizeof(float), 0);

    dim3 ggrid(S / 64, 2);
    gemm_logits<<<ggrid, 128>>>(x, wg, D, S);
    softmax_top1<<<S / 8, 256>>>(S);
    scan_laux<<<1, 1024>>>(S, S / 8);
    scatter_out<<<(S + 255) / 256, 256>>>((float*)d_out, S, C, comb, disp, aux);
}